// round 2
// baseline (speedup 1.0000x reference)
#include <cuda_runtime.h>
#include <math.h>

#define NN 50000
#define EE 400000
#define D_IN 128
#define D_HID 128
#define D_OUT 64

// ---------------- scratch (static device globals; no allocation allowed) ----------------
__device__ float g_Q0[4][NN * D_HID];
__device__ float g_K0[4][NN * D_HID];
__device__ float g_V0[4][NN * D_HID];
__device__ float g_H[NN * D_HID];
__device__ float g_Q1[2][NN * D_OUT];
__device__ float g_K1[2][NN * D_OUT];
__device__ float g_V1[2][NN * D_OUT];
__device__ int g_deg[2][NN];
__device__ int g_scan[2][NN];
__device__ int g_bsum[2][256];
__device__ int g_boff[2][256];
__device__ int g_cursor[2][NN];
__device__ int g_rowptr[2][NN + 1];
__device__ int g_cols[2][EE];

// ---------------- CSR build (both hops batched per kernel) ----------------
__global__ void zero2_kernel(int n) {
    int i = blockIdx.x * blockDim.x + threadIdx.x;
    if (i < n) g_deg[blockIdx.y][i] = 0;
}

__global__ void count2_kernel(const int* __restrict__ e0, const int* __restrict__ e1, int e) {
    int i = blockIdx.x * blockDim.x + threadIdx.x;
    int hop = blockIdx.y;
    const int* rows = hop ? e1 : e0;
    if (i < e) atomicAdd(&g_deg[hop][rows[i]], 1);
}

// per-256-block exclusive scan + block partial sums
__global__ void scanA_kernel(int n) {
    int hop = blockIdx.y;
    int chunk = blockIdx.x;
    int tid = threadIdx.x;
    int i = chunk * 256 + tid;
    int v = (i < n) ? g_deg[hop][i] : 0;
    __shared__ int sm[256];
    sm[tid] = v;
    __syncthreads();
#pragma unroll
    for (int off = 1; off < 256; off <<= 1) {
        int t = (tid >= off) ? sm[tid - off] : 0;
        __syncthreads();
        sm[tid] += t;
        __syncthreads();
    }
    if (i < n) g_scan[hop][i] = sm[tid] - v;  // exclusive within block
    if (tid == 255) g_bsum[hop][chunk] = sm[255];
}

// single-block scan of block partials (nblk <= 256), both hops
__global__ void scanB_kernel(int nblk) {
    __shared__ int sm[256];
    int tid = threadIdx.x;
    for (int hop = 0; hop < 2; hop++) {
        int v = (tid < nblk) ? g_bsum[hop][tid] : 0;
        sm[tid] = v;
        __syncthreads();
#pragma unroll
        for (int off = 1; off < 256; off <<= 1) {
            int t = (tid >= off) ? sm[tid - off] : 0;
            __syncthreads();
            sm[tid] += t;
            __syncthreads();
        }
        if (tid < nblk) g_boff[hop][tid] = sm[tid] - v;  // exclusive
        __syncthreads();
    }
}

__global__ void scanC_kernel(int n, int e) {
    int i = blockIdx.x * blockDim.x + threadIdx.x;
    int hop = blockIdx.y;
    if (i < n) {
        int rp = g_scan[hop][i] + g_boff[hop][i >> 8];
        g_rowptr[hop][i] = rp;
        g_cursor[hop][i] = rp;
        if (i == 0) g_rowptr[hop][n] = e;
    }
}

__global__ void scatter2_kernel(const int* __restrict__ e0, const int* __restrict__ e1, int e) {
    int i = blockIdx.x * blockDim.x + threadIdx.x;
    int hop = blockIdx.y;
    const int* rows = hop ? e1 : e0;
    if (i < e) {
        int r = rows[i];
        int c = rows[i + e];
        int p = atomicAdd(&g_cursor[hop][r], 1);
        g_cols[hop][p] = c;
    }
}

// ---------------- batched QKV GEMM with register-prefetch pipelining ----------------
// blockIdx.z = combo*3 + {q,k,v}. KD=128 fixed -> fully unrolled k-loop.
template <int LAYER, int BM, int BN, int BK, int TM, int TN>
__global__ void __launch_bounds__(256) qkv_gemm_kernel(
    const float* __restrict__ Xin,
    const float* __restrict__ Wq, const float* __restrict__ Wk, const float* __restrict__ Wv,
    const float* __restrict__ bq, const float* __restrict__ bk, const float* __restrict__ bv,
    int M) {
    constexpr int KD = 128;
    constexpr int THREADS = (BM / TM) * (BN / TN);
    constexpr int APR = BK / 4;
    constexpr int BPR = BN / 4;
    constexpr int AL = (BM * BK) / (4 * THREADS);
    constexpr int BL = (BK * BN) / (4 * THREADS);
    constexpr int NIT = KD / BK;

    const float* X = (LAYER == 0) ? Xin : (const float*)g_H;
    int z = blockIdx.z;
    int c = z / 3, mm = z % 3;
    const float* W = (mm == 0 ? Wq : (mm == 1 ? Wk : Wv)) + (size_t)c * KD * BN;
    const float* bias = (mm == 0 ? bq : (mm == 1 ? bk : bv)) + (size_t)c * BN;
    float* O;
    if (LAYER == 0) O = (mm == 0 ? g_Q0[c] : (mm == 1 ? g_K0[c] : g_V0[c]));
    else            O = (mm == 0 ? g_Q1[c] : (mm == 1 ? g_K1[c] : g_V1[c]));

    __shared__ float As[BK][BM + 4];
    __shared__ float Bs[BK][BN];
    int tid = threadIdx.x;
    int tx = tid % (BN / TN);
    int ty = tid / (BN / TN);
    int row0 = blockIdx.x * BM;

    float acc[TM][TN];
#pragma unroll
    for (int i = 0; i < TM; i++)
#pragma unroll
        for (int j = 0; j < TN; j++) acc[i][j] = 0.f;

    float4 pa[AL], pb[BL];

    // initial tile load (k0 = 0)
#pragma unroll
    for (int i = 0; i < AL; i++) {
        int f = tid + i * THREADS;
        int r = f / APR, kc = (f % APR) * 4;
        int gr = row0 + r;
        pa[i] = (gr < M) ? *(const float4*)(X + (size_t)gr * KD + kc)
                         : make_float4(0.f, 0.f, 0.f, 0.f);
    }
#pragma unroll
    for (int i = 0; i < BL; i++) {
        int f = tid + i * THREADS;
        int r = f / BPR, nc = (f % BPR) * 4;
        pb[i] = *(const float4*)(W + (size_t)r * BN + nc);
    }

#pragma unroll
    for (int it = 0; it < NIT; it++) {
        // commit prefetched regs to smem
#pragma unroll
        for (int i = 0; i < AL; i++) {
            int f = tid + i * THREADS;
            int r = f / APR, kc = (f % APR) * 4;
            As[kc + 0][r] = pa[i].x; As[kc + 1][r] = pa[i].y;
            As[kc + 2][r] = pa[i].z; As[kc + 3][r] = pa[i].w;
        }
#pragma unroll
        for (int i = 0; i < BL; i++) {
            int f = tid + i * THREADS;
            int r = f / BPR, nc = (f % BPR) * 4;
            *(float4*)&Bs[r][nc] = pb[i];
        }
        __syncthreads();

        // prefetch next tile while computing this one
        if (it + 1 < NIT) {
            int k0 = (it + 1) * BK;
#pragma unroll
            for (int i = 0; i < AL; i++) {
                int f = tid + i * THREADS;
                int r = f / APR, kc = (f % APR) * 4;
                int gr = row0 + r;
                pa[i] = (gr < M) ? *(const float4*)(X + (size_t)gr * KD + k0 + kc)
                                 : make_float4(0.f, 0.f, 0.f, 0.f);
            }
#pragma unroll
            for (int i = 0; i < BL; i++) {
                int f = tid + i * THREADS;
                int r = f / BPR, nc = (f % BPR) * 4;
                pb[i] = *(const float4*)(W + (size_t)(k0 + r) * BN + nc);
            }
        }

#pragma unroll
        for (int kk = 0; kk < BK; kk++) {
            float ra[TM], rb[TN];
#pragma unroll
            for (int i = 0; i < TM; i++) ra[i] = As[kk][ty * TM + i];
#pragma unroll
            for (int j = 0; j < TN; j++) rb[j] = Bs[kk][tx * TN + j];
#pragma unroll
            for (int i = 0; i < TM; i++)
#pragma unroll
                for (int j = 0; j < TN; j++) acc[i][j] += ra[i] * rb[j];
        }
        __syncthreads();
    }

#pragma unroll
    for (int i = 0; i < TM; i++) {
        int gr = row0 + ty * TM + i;
        if (gr < M) {
#pragma unroll
            for (int j = 0; j < TN; j += 4) {
                int col = tx * TN + j;
                float4 o;
                o.x = acc[i][j + 0] + bias[col + 0];
                o.y = acc[i][j + 1] + bias[col + 1];
                o.z = acc[i][j + 2] + bias[col + 2];
                o.w = acc[i][j + 3] + bias[col + 3];
                *(float4*)(O + (size_t)gr * BN + col) = o;
            }
        }
    }
}

// ---------------- layer-0 fused attention: 2 combos (same hop) per warp ----------------
// D=128, 4 heads x 32 dims -> 8 lanes/head, 4 floats/lane. Online softmax.
// mode 0: g_H = beta*(yA+yB);  mode 1: g_H = elu(g_H + beta*(yA+yB))
__global__ void attn0_pair_kernel(int cA, int cB, int hop, float beta, int mode, int n) {
    int gw = (blockIdx.x * blockDim.x + threadIdx.x) >> 5;
    if (gw >= n) return;
    int lane = threadIdx.x & 31;
    const float* __restrict__ QA = g_Q0[cA];
    const float* __restrict__ KA = g_K0[cA];
    const float* __restrict__ VA = g_V0[cA];
    const float* __restrict__ QB = g_Q0[cB];
    const float* __restrict__ KB = g_K0[cB];
    const float* __restrict__ VB = g_V0[cB];
    const float scale = 0.17677669529663687f;  // 1/sqrt(32)

    size_t off = (size_t)gw * 128 + lane * 4;
    float4 qa = *(const float4*)(QA + off);
    float4 qb = *(const float4*)(QB + off);
    float4 aA = make_float4(0.f, 0.f, 0.f, 0.f);
    float4 aB = make_float4(0.f, 0.f, 0.f, 0.f);
    float mA = -INFINITY, lA = 0.f, mB = -INFINITY, lB = 0.f;

    int s0 = g_rowptr[hop][gw], s1 = g_rowptr[hop][gw + 1];
    for (int p = s0; p < s1; p++) {
        int cidx = g_cols[hop][p];
        size_t co = (size_t)cidx * 128 + lane * 4;
        float4 ka = *(const float4*)(KA + co);
        float4 kb = *(const float4*)(KB + co);
        float dA = qa.x * ka.x + qa.y * ka.y + qa.z * ka.z + qa.w * ka.w;
        float dB = qb.x * kb.x + qb.y * kb.y + qb.z * kb.z + qb.w * kb.w;
        dA += __shfl_xor_sync(0xffffffffu, dA, 1);
        dA += __shfl_xor_sync(0xffffffffu, dA, 2);
        dA += __shfl_xor_sync(0xffffffffu, dA, 4);
        dB += __shfl_xor_sync(0xffffffffu, dB, 1);
        dB += __shfl_xor_sync(0xffffffffu, dB, 2);
        dB += __shfl_xor_sync(0xffffffffu, dB, 4);
        float4 va = *(const float4*)(VA + co);
        float4 vb = *(const float4*)(VB + co);
        {
            float s = dA * scale;
            float nm = fmaxf(mA, s);
            float sc = __expf(mA - nm);
            float pe = __expf(s - nm);
            lA = lA * sc + pe;
            aA.x = aA.x * sc + pe * va.x; aA.y = aA.y * sc + pe * va.y;
            aA.z = aA.z * sc + pe * va.z; aA.w = aA.w * sc + pe * va.w;
            mA = nm;
        }
        {
            float s = dB * scale;
            float nm = fmaxf(mB, s);
            float sc = __expf(mB - nm);
            float pe = __expf(s - nm);
            lB = lB * sc + pe;
            aB.x = aB.x * sc + pe * vb.x; aB.y = aB.y * sc + pe * vb.y;
            aB.z = aB.z * sc + pe * vb.z; aB.w = aB.w * sc + pe * vb.w;
            mB = nm;
        }
    }
    float wA = beta / (lA + 1e-16f);
    float wB = beta / (lB + 1e-16f);
    float4 y;
    y.x = aA.x * wA + aB.x * wB;
    y.y = aA.y * wA + aB.y * wB;
    y.z = aA.z * wA + aB.z * wB;
    y.w = aA.w * wA + aB.w * wB;
    float* op = g_H + off;
    if (mode == 0) {
        *(float4*)op = y;
    } else {
        float4 cur = *(float4*)op;
        cur.x += y.x; cur.y += y.y; cur.z += y.z; cur.w += y.w;
        cur.x = cur.x > 0.f ? cur.x : expm1f(cur.x);
        cur.y = cur.y > 0.f ? cur.y : expm1f(cur.y);
        cur.z = cur.z > 0.f ? cur.z : expm1f(cur.z);
        cur.w = cur.w > 0.f ? cur.w : expm1f(cur.w);
        *(float4*)op = cur;
    }
}

// ---------------- layer-1 attention: D=64, 4 heads x 16 dims -> 8 lanes/head, 2 floats/lane
// mode 0: out = y;  mode 1: out = log_softmax(out + beta*y)
__global__ void attn1_kernel(int combo, int hop, float beta, int mode,
                             float* __restrict__ out, int n) {
    int gw = (blockIdx.x * blockDim.x + threadIdx.x) >> 5;
    if (gw >= n) return;
    int lane = threadIdx.x & 31;
    const float* __restrict__ Q = g_Q1[combo];
    const float* __restrict__ Kp = g_K1[combo];
    const float* __restrict__ Vp = g_V1[combo];
    const float scale = 0.25f;  // 1/sqrt(16)

    size_t off = (size_t)gw * 64 + lane * 2;
    float2 q = *(const float2*)(Q + off);
    float2 acc = make_float2(0.f, 0.f);
    float m = -INFINITY, l = 0.f;

    int s0 = g_rowptr[hop][gw], s1 = g_rowptr[hop][gw + 1];
    for (int p = s0; p < s1; p++) {
        int cidx = g_cols[hop][p];
        size_t co = (size_t)cidx * 64 + lane * 2;
        float2 k = *(const float2*)(Kp + co);
        float d = q.x * k.x + q.y * k.y;
        d += __shfl_xor_sync(0xffffffffu, d, 1);
        d += __shfl_xor_sync(0xffffffffu, d, 2);
        d += __shfl_xor_sync(0xffffffffu, d, 4);
        float2 v = *(const float2*)(Vp + co);
        float s = d * scale;
        float nm = fmaxf(m, s);
        float sc = __expf(m - nm);
        float pe = __expf(s - nm);
        l = l * sc + pe;
        acc.x = acc.x * sc + pe * v.x;
        acc.y = acc.y * sc + pe * v.y;
        m = nm;
    }
    float w = beta / (l + 1e-16f);
    float2 y = make_float2(acc.x * w, acc.y * w);
    float* op = out + off;
    if (mode == 0) {
        *(float2*)op = y;
    } else {
        float2 cur = *(float2*)op;
        cur.x += y.x; cur.y += y.y;
        // warp log_softmax over the 64-dim row
        float mx = fmaxf(cur.x, cur.y);
#pragma unroll
        for (int o = 16; o; o >>= 1) mx = fmaxf(mx, __shfl_xor_sync(0xffffffffu, mx, o));
        float s = expf(cur.x - mx) + expf(cur.y - mx);
#pragma unroll
        for (int o = 16; o; o >>= 1) s += __shfl_xor_sync(0xffffffffu, s, o);
        float lg = mx + logf(s);
        cur.x -= lg; cur.y -= lg;
        *(float2*)op = cur;
    }
}

// ---------------- launch ----------------
extern "C" void kernel_launch(void* const* d_in, const int* in_sizes, int n_in,
                              void* d_out, int out_size) {
    const float* x   = (const float*)d_in[0];
    const int* edge0 = (const int*)d_in[1];
    const int* edge1 = (const int*)d_in[2];
    const float* W0q = (const float*)d_in[3];
    const float* W0k = (const float*)d_in[4];
    const float* W0v = (const float*)d_in[5];
    const float* b0q = (const float*)d_in[6];
    const float* b0k = (const float*)d_in[7];
    const float* b0v = (const float*)d_in[8];
    const float* W1q = (const float*)d_in[9];
    const float* W1k = (const float*)d_in[10];
    const float* W1v = (const float*)d_in[11];
    const float* b1q = (const float*)d_in[12];
    const float* b1k = (const float*)d_in[13];
    const float* b1v = (const float*)d_in[14];
    float* out = (float*)d_out;

    int M = in_sizes[0] / D_IN;   // 50000
    int E = in_sizes[1] / 2;      // 400000
    int nb = (M + 255) / 256;
    int eb = (E + 255) / 256;

    // CSR build (launches 0-4), then layer-0 GEMM at launch index 5 (ncu -s 5 -c 1 target)
    zero2_kernel<<<dim3(nb, 2), 256>>>(M);                       // 0
    count2_kernel<<<dim3(eb, 2), 256>>>(edge0, edge1, E);        // 1
    scanA_kernel<<<dim3(nb, 2), 256>>>(M);                       // 2
    scanB_kernel<<<1, 256>>>(nb);                                // 3
    scanC_kernel<<<dim3(nb, 2), 256>>>(M, E);                    // 4

    dim3 g0((M + 127) / 128, 1, 12);
    qkv_gemm_kernel<0, 128, 128, 16, 8, 8><<<g0, 256>>>(         // 5  <- profiled
        x, W0q, W0k, W0v, b0q, b0k, b0v, M);

    scatter2_kernel<<<dim3(eb, 2), 256>>>(edge0, edge1, E);      // 6

    int ab = (M * 32 + 255) / 256;
    // layer 0: hop0 combos {0,2} beta=1, hop1 combos {1,3} beta=0.25 (+add+ELU)
    attn0_pair_kernel<<<ab, 256>>>(0, 2, 0, 1.0f, 0, M);         // 7
    attn0_pair_kernel<<<ab, 256>>>(1, 3, 1, 0.25f, 1, M);        // 8

    dim3 g1((M + 127) / 128, 1, 6);
    qkv_gemm_kernel<1, 128, 64, 16, 8, 4><<<g1, 256>>>(          // 9
        x, W1q, W1k, W1v, b1q, b1k, b1v, M);

    // layer 1: combo0=hop0 (store), combo1=hop1 (accumulate + log_softmax)
    attn1_kernel<<<ab, 256>>>(0, 0, 1.0f, 0, out, M);            // 10
    attn1_kernel<<<ab, 256>>>(1, 1, 0.25f, 1, out, M);           // 11
}

// round 3
// speedup vs baseline: 1.4709x; 1.4709x over previous
#include <cuda_runtime.h>
#include <math.h>

#define NN 50000
#define EE 400000
#define D_IN 128
#define D_HID 128
#define D_OUT 64

// ---------------- scratch (static device globals; no allocation allowed) ----------------
__device__ float g_Q0[4][NN * D_HID];
__device__ float g_K0[4][NN * D_HID];
__device__ float g_V0[4][NN * D_HID];
__device__ float g_H[NN * D_HID];
__device__ float g_Q1[2][NN * D_OUT];
__device__ float g_K1[2][NN * D_OUT];
__device__ float g_V1[2][NN * D_OUT];
__device__ int g_deg[2][NN];
__device__ int g_scan[2][NN];
__device__ int g_bsum[2][256];
__device__ int g_boff[2][256];
__device__ int g_cursor[2][NN];
__device__ int g_rowptr[2][NN + 1];
__device__ int g_cols[2][EE];

// ---------------- CSR build (both hops batched per kernel) ----------------
__global__ void zero2_kernel(int n) {
    int i = blockIdx.x * blockDim.x + threadIdx.x;
    if (i < n) g_deg[blockIdx.y][i] = 0;
}

__global__ void count2_kernel(const int* __restrict__ e0, const int* __restrict__ e1, int e) {
    int i = blockIdx.x * blockDim.x + threadIdx.x;
    int hop = blockIdx.y;
    const int* rows = hop ? e1 : e0;
    if (i < e) atomicAdd(&g_deg[hop][rows[i]], 1);
}

// per-256-block exclusive scan + block partial sums
__global__ void scanA_kernel(int n) {
    int hop = blockIdx.y;
    int chunk = blockIdx.x;
    int tid = threadIdx.x;
    int i = chunk * 256 + tid;
    int v = (i < n) ? g_deg[hop][i] : 0;
    __shared__ int sm[256];
    sm[tid] = v;
    __syncthreads();
#pragma unroll
    for (int off = 1; off < 256; off <<= 1) {
        int t = (tid >= off) ? sm[tid - off] : 0;
        __syncthreads();
        sm[tid] += t;
        __syncthreads();
    }
    if (i < n) g_scan[hop][i] = sm[tid] - v;  // exclusive within block
    if (tid == 255) g_bsum[hop][chunk] = sm[255];
}

// single-block scan of block partials (nblk <= 256), both hops
__global__ void scanB_kernel(int nblk) {
    __shared__ int sm[256];
    int tid = threadIdx.x;
    for (int hop = 0; hop < 2; hop++) {
        int v = (tid < nblk) ? g_bsum[hop][tid] : 0;
        sm[tid] = v;
        __syncthreads();
#pragma unroll
        for (int off = 1; off < 256; off <<= 1) {
            int t = (tid >= off) ? sm[tid - off] : 0;
            __syncthreads();
            sm[tid] += t;
            __syncthreads();
        }
        if (tid < nblk) g_boff[hop][tid] = sm[tid] - v;  // exclusive
        __syncthreads();
    }
}

__global__ void scanC_kernel(int n, int e) {
    int i = blockIdx.x * blockDim.x + threadIdx.x;
    int hop = blockIdx.y;
    if (i < n) {
        int rp = g_scan[hop][i] + g_boff[hop][i >> 8];
        g_rowptr[hop][i] = rp;
        g_cursor[hop][i] = rp;
        if (i == 0) g_rowptr[hop][n] = e;
    }
}

__global__ void scatter2_kernel(const int* __restrict__ e0, const int* __restrict__ e1, int e) {
    int i = blockIdx.x * blockDim.x + threadIdx.x;
    int hop = blockIdx.y;
    const int* rows = hop ? e1 : e0;
    if (i < e) {
        int r = rows[i];
        int c = rows[i + e];
        int p = atomicAdd(&g_cursor[hop][r], 1);
        g_cols[hop][p] = c;
    }
}

// ---------------- batched QKV GEMM (R1-proven version: no prefetch, no outer unroll) ----
// blockIdx.z = combo*3 + {q,k,v}.
template <int LAYER, int BM, int BN, int BK, int TM, int TN>
__global__ void __launch_bounds__(256) qkv_gemm_kernel(
    const float* __restrict__ Xin,
    const float* __restrict__ Wq, const float* __restrict__ Wk, const float* __restrict__ Wv,
    const float* __restrict__ bq, const float* __restrict__ bk, const float* __restrict__ bv,
    int M, int Kd) {
    constexpr int THREADS = (BM / TM) * (BN / TN);
    const float* X = (LAYER == 0) ? Xin : (const float*)g_H;
    int z = blockIdx.z;
    int c = z / 3, mm = z % 3;
    const float* W = (mm == 0 ? Wq : (mm == 1 ? Wk : Wv)) + (size_t)c * Kd * BN;
    const float* bias = (mm == 0 ? bq : (mm == 1 ? bk : bv)) + (size_t)c * BN;
    float* O;
    if (LAYER == 0) O = (mm == 0 ? g_Q0[c] : (mm == 1 ? g_K0[c] : g_V0[c]));
    else            O = (mm == 0 ? g_Q1[c] : (mm == 1 ? g_K1[c] : g_V1[c]));

    __shared__ float As[BK][BM + 4];
    __shared__ float Bs[BK][BN];
    int tid = threadIdx.x;
    int tx = tid % (BN / TN);
    int ty = tid / (BN / TN);
    int row0 = blockIdx.x * BM;

    float acc[TM][TN];
#pragma unroll
    for (int i = 0; i < TM; i++)
#pragma unroll
        for (int j = 0; j < TN; j++) acc[i][j] = 0.f;

    constexpr int APR = BK / 4;  // float4 slots per A row
    constexpr int BPR = BN / 4;  // float4 slots per B row

#pragma unroll 1
    for (int k0 = 0; k0 < Kd; k0 += BK) {
#pragma unroll
        for (int r = tid / APR; r < BM; r += THREADS / APR) {
            int kc = (tid % APR) * 4;
            int gr = row0 + r;
            float4 a = (gr < M) ? *(const float4*)(X + (size_t)gr * Kd + k0 + kc)
                                : make_float4(0.f, 0.f, 0.f, 0.f);
            As[kc + 0][r] = a.x; As[kc + 1][r] = a.y;
            As[kc + 2][r] = a.z; As[kc + 3][r] = a.w;
        }
#pragma unroll
        for (int r = tid / BPR; r < BK; r += (THREADS / BPR > 0 ? THREADS / BPR : 1)) {
            int nc = (tid % BPR) * 4;
            *(float4*)&Bs[r][nc] = *(const float4*)(W + (size_t)(k0 + r) * BN + nc);
        }
        __syncthreads();
#pragma unroll
        for (int kk = 0; kk < BK; kk++) {
            float ra[TM], rb[TN];
#pragma unroll
            for (int i = 0; i < TM; i++) ra[i] = As[kk][ty * TM + i];
#pragma unroll
            for (int j = 0; j < TN; j++) rb[j] = Bs[kk][tx * TN + j];
#pragma unroll
            for (int i = 0; i < TM; i++)
#pragma unroll
                for (int j = 0; j < TN; j++) acc[i][j] += ra[i] * rb[j];
        }
        __syncthreads();
    }
#pragma unroll
    for (int i = 0; i < TM; i++) {
        int gr = row0 + ty * TM + i;
        if (gr < M) {
#pragma unroll
            for (int j = 0; j < TN; j += 4) {
                int col = tx * TN + j;
                float4 o;
                o.x = acc[i][j + 0] + bias[col + 0];
                o.y = acc[i][j + 1] + bias[col + 1];
                o.z = acc[i][j + 2] + bias[col + 2];
                o.w = acc[i][j + 3] + bias[col + 3];
                *(float4*)(O + (size_t)gr * BN + col) = o;
            }
        }
    }
}

// ---------------- layer-0 fused attention: 2 combos (same hop) per warp ----------------
// D=128, 4 heads x 32 dims -> 8 lanes/head, 4 floats/lane. Online softmax.
// mode 0: g_H = beta*(yA+yB);  mode 1: g_H = elu(g_H + beta*(yA+yB))
__global__ void attn0_pair_kernel(int cA, int cB, int hop, float beta, int mode, int n) {
    int gw = (blockIdx.x * blockDim.x + threadIdx.x) >> 5;
    if (gw >= n) return;
    int lane = threadIdx.x & 31;
    const float* __restrict__ QA = g_Q0[cA];
    const float* __restrict__ KA = g_K0[cA];
    const float* __restrict__ VA = g_V0[cA];
    const float* __restrict__ QB = g_Q0[cB];
    const float* __restrict__ KB = g_K0[cB];
    const float* __restrict__ VB = g_V0[cB];
    const float scale = 0.17677669529663687f;  // 1/sqrt(32)

    size_t off = (size_t)gw * 128 + lane * 4;
    float4 qa = *(const float4*)(QA + off);
    float4 qb = *(const float4*)(QB + off);
    float4 aA = make_float4(0.f, 0.f, 0.f, 0.f);
    float4 aB = make_float4(0.f, 0.f, 0.f, 0.f);
    float mA = -INFINITY, lA = 0.f, mB = -INFINITY, lB = 0.f;

    int s0 = g_rowptr[hop][gw], s1 = g_rowptr[hop][gw + 1];
    for (int p = s0; p < s1; p++) {
        int cidx = g_cols[hop][p];
        size_t co = (size_t)cidx * 128 + lane * 4;
        float4 ka = *(const float4*)(KA + co);
        float4 kb = *(const float4*)(KB + co);
        float dA = qa.x * ka.x + qa.y * ka.y + qa.z * ka.z + qa.w * ka.w;
        float dB = qb.x * kb.x + qb.y * kb.y + qb.z * kb.z + qb.w * kb.w;
        dA += __shfl_xor_sync(0xffffffffu, dA, 1);
        dA += __shfl_xor_sync(0xffffffffu, dA, 2);
        dA += __shfl_xor_sync(0xffffffffu, dA, 4);
        dB += __shfl_xor_sync(0xffffffffu, dB, 1);
        dB += __shfl_xor_sync(0xffffffffu, dB, 2);
        dB += __shfl_xor_sync(0xffffffffu, dB, 4);
        float4 va = *(const float4*)(VA + co);
        float4 vb = *(const float4*)(VB + co);
        {
            float s = dA * scale;
            float nm = fmaxf(mA, s);
            float sc = __expf(mA - nm);
            float pe = __expf(s - nm);
            lA = lA * sc + pe;
            aA.x = aA.x * sc + pe * va.x; aA.y = aA.y * sc + pe * va.y;
            aA.z = aA.z * sc + pe * va.z; aA.w = aA.w * sc + pe * va.w;
            mA = nm;
        }
        {
            float s = dB * scale;
            float nm = fmaxf(mB, s);
            float sc = __expf(mB - nm);
            float pe = __expf(s - nm);
            lB = lB * sc + pe;
            aB.x = aB.x * sc + pe * vb.x; aB.y = aB.y * sc + pe * vb.y;
            aB.z = aB.z * sc + pe * vb.z; aB.w = aB.w * sc + pe * vb.w;
            mB = nm;
        }
    }
    float wA = beta / (lA + 1e-16f);
    float wB = beta / (lB + 1e-16f);
    float4 y;
    y.x = aA.x * wA + aB.x * wB;
    y.y = aA.y * wA + aB.y * wB;
    y.z = aA.z * wA + aB.z * wB;
    y.w = aA.w * wA + aB.w * wB;
    float* op = g_H + off;
    if (mode == 0) {
        *(float4*)op = y;
    } else {
        float4 cur = *(float4*)op;
        cur.x += y.x; cur.y += y.y; cur.z += y.z; cur.w += y.w;
        cur.x = cur.x > 0.f ? cur.x : expm1f(cur.x);
        cur.y = cur.y > 0.f ? cur.y : expm1f(cur.y);
        cur.z = cur.z > 0.f ? cur.z : expm1f(cur.z);
        cur.w = cur.w > 0.f ? cur.w : expm1f(cur.w);
        *(float4*)op = cur;
    }
}

// ---------------- layer-1 attention: D=64, 4 heads x 16 dims -> 8 lanes/head, 2 floats/lane
// mode 0: out = y;  mode 1: out = log_softmax(out + beta*y)
__global__ void attn1_kernel(int combo, int hop, float beta, int mode,
                             float* __restrict__ out, int n) {
    int gw = (blockIdx.x * blockDim.x + threadIdx.x) >> 5;
    if (gw >= n) return;
    int lane = threadIdx.x & 31;
    const float* __restrict__ Q = g_Q1[combo];
    const float* __restrict__ Kp = g_K1[combo];
    const float* __restrict__ Vp = g_V1[combo];
    const float scale = 0.25f;  // 1/sqrt(16)

    size_t off = (size_t)gw * 64 + lane * 2;
    float2 q = *(const float2*)(Q + off);
    float2 acc = make_float2(0.f, 0.f);
    float m = -INFINITY, l = 0.f;

    int s0 = g_rowptr[hop][gw], s1 = g_rowptr[hop][gw + 1];
    for (int p = s0; p < s1; p++) {
        int cidx = g_cols[hop][p];
        size_t co = (size_t)cidx * 64 + lane * 2;
        float2 k = *(const float2*)(Kp + co);
        float d = q.x * k.x + q.y * k.y;
        d += __shfl_xor_sync(0xffffffffu, d, 1);
        d += __shfl_xor_sync(0xffffffffu, d, 2);
        d += __shfl_xor_sync(0xffffffffu, d, 4);
        float2 v = *(const float2*)(Vp + co);
        float s = d * scale;
        float nm = fmaxf(m, s);
        float sc = __expf(m - nm);
        float pe = __expf(s - nm);
        l = l * sc + pe;
        acc.x = acc.x * sc + pe * v.x;
        acc.y = acc.y * sc + pe * v.y;
        m = nm;
    }
    float w = beta / (l + 1e-16f);
    float2 y = make_float2(acc.x * w, acc.y * w);
    float* op = out + off;
    if (mode == 0) {
        *(float2*)op = y;
    } else {
        float2 cur = *(float2*)op;
        cur.x += y.x; cur.y += y.y;
        // warp log_softmax over the 64-dim row
        float mx = fmaxf(cur.x, cur.y);
#pragma unroll
        for (int o = 16; o; o >>= 1) mx = fmaxf(mx, __shfl_xor_sync(0xffffffffu, mx, o));
        float s = expf(cur.x - mx) + expf(cur.y - mx);
#pragma unroll
        for (int o = 16; o; o >>= 1) s += __shfl_xor_sync(0xffffffffu, s, o);
        float lg = mx + logf(s);
        cur.x -= lg; cur.y -= lg;
        *(float2*)op = cur;
    }
}

// ---------------- launch ----------------
extern "C" void kernel_launch(void* const* d_in, const int* in_sizes, int n_in,
                              void* d_out, int out_size) {
    const float* x   = (const float*)d_in[0];
    const int* edge0 = (const int*)d_in[1];
    const int* edge1 = (const int*)d_in[2];
    const float* W0q = (const float*)d_in[3];
    const float* W0k = (const float*)d_in[4];
    const float* W0v = (const float*)d_in[5];
    const float* b0q = (const float*)d_in[6];
    const float* b0k = (const float*)d_in[7];
    const float* b0v = (const float*)d_in[8];
    const float* W1q = (const float*)d_in[9];
    const float* W1k = (const float*)d_in[10];
    const float* W1v = (const float*)d_in[11];
    const float* b1q = (const float*)d_in[12];
    const float* b1k = (const float*)d_in[13];
    const float* b1v = (const float*)d_in[14];
    float* out = (float*)d_out;

    int M = in_sizes[0] / D_IN;   // 50000
    int E = in_sizes[1] / 2;      // 400000
    int nb = (M + 255) / 256;
    int eb = (E + 255) / 256;

    zero2_kernel<<<dim3(nb, 2), 256>>>(M);                       // 0
    count2_kernel<<<dim3(eb, 2), 256>>>(edge0, edge1, E);        // 1
    scanA_kernel<<<dim3(nb, 2), 256>>>(M);                       // 2
    scanB_kernel<<<1, 256>>>(nb);                                // 3
    scanC_kernel<<<dim3(nb, 2), 256>>>(M, E);                    // 4

    dim3 g0((M + 127) / 128, 1, 12);
    qkv_gemm_kernel<0, 128, 128, 16, 8, 8><<<g0, 256>>>(         // 5
        x, W0q, W0k, W0v, b0q, b0k, b0v, M, D_IN);

    scatter2_kernel<<<dim3(eb, 2), 256>>>(edge0, edge1, E);      // 6

    int ab = (M * 32 + 255) / 256;
    // layer 0: hop0 combos {0,2} beta=1, hop1 combos {1,3} beta=0.25 (+add+ELU)
    attn0_pair_kernel<<<ab, 256>>>(0, 2, 0, 1.0f, 0, M);         // 7
    attn0_pair_kernel<<<ab, 256>>>(1, 3, 1, 0.25f, 1, M);        // 8

    dim3 g1((M + 127) / 128, 1, 6);
    qkv_gemm_kernel<1, 128, 64, 16, 8, 4><<<g1, 256>>>(          // 9
        x, W1q, W1k, W1v, b1q, b1k, b1v, M, D_HID);

    // layer 1: combo0=hop0 (store), combo1=hop1 (accumulate + log_softmax)
    attn1_kernel<<<ab, 256>>>(0, 0, 1.0f, 0, out, M);            // 10
    attn1_kernel<<<ab, 256>>>(1, 1, 0.25f, 1, out, M);           // 11
}